// round 15
// baseline (speedup 1.0000x reference)
#include <cuda_runtime.h>
#include <cstdint>

#define HH 264
#define WW 264
#define HWP (HH*WW)      // 69696
#define C 96
#define C3 288
#define SHIFT 4

typedef unsigned long long ull;

// ---- scratch (static device globals; allocation is forbidden) ----
__device__ float g_qkv[C3 * HWP];        // after 1x1 conv (shifted frame)
__device__ float g_dw [C3 * HWP];        // after depthwise 3x3
__device__ float g_out[25 * C * 4096];   // per-tile attention output
__device__ float g_wT [C * C3];          // qkv_w transposed [k][oc]
__device__ float g_pwT[C * C];           // proj_w transposed [k][oc]

__constant__ int c_off[5] = {0, 50, 100, 150, 200};

// ---- tf32 split helper (3xTF32 trick) ----
__device__ __forceinline__ void tf32_split(float v, float& hi, float& lo) {
    uint32_t hb;
    asm("cvt.rna.tf32.f32 %0, %1;" : "=r"(hb) : "f"(v));
    hi = __uint_as_float(hb);
    float r = v - hi;
    uint32_t lb;
    asm("cvt.rna.tf32.f32 %0, %1;" : "=r"(lb) : "f"(r));
    lo = __uint_as_float(lb);
}

#define MMA_TF32(c, a, b0, b1) \
    asm volatile("mma.sync.aligned.m16n8k8.row.col.f32.tf32.tf32.f32 " \
        "{%0,%1,%2,%3}, {%4,%5,%6,%7}, {%8,%9}, {%0,%1,%2,%3};" \
        : "+f"((c)[0]), "+f"((c)[1]), "+f"((c)[2]), "+f"((c)[3]) \
        : "r"((a)[0]), "r"((a)[1]), "r"((a)[2]), "r"((a)[3]), \
          "r"(b0), "r"(b1))

__device__ __forceinline__ uint32_t fb(float v) { return __float_as_uint(v); }

// --------------------------------------------------------------------------
// K0: transpose the two weight matrices once (tiny)
// --------------------------------------------------------------------------
__global__ void transpose_w_kernel(const float* __restrict__ qkvw,
                                   const float* __restrict__ pw)
{
    int i = blockIdx.x * 256 + threadIdx.x;
    if (i < C3 * C) { int oc = i / C, k = i % C; g_wT [k * C3 + oc] = qkvw[i]; }
    if (i < C  * C) { int oc = i / C, k = i % C; g_pwT[k * C  + oc] = pw[i]; }
}

// --------------------------------------------------------------------------
// K1: qkv = qkv_w @ x_shifted via mma.sync tf32 (3xTF32 = fp32 accuracy).
// --------------------------------------------------------------------------
#define XS 136
#define WS2 104
__global__ __launch_bounds__(256, 2) void qkv_mma_kernel(const float* __restrict__ x)
{
    __shared__ float sXhi[16 * XS], sXlo[16 * XS];
    __shared__ float sWhi[16 * WS2], sWlo[16 * WS2];
    __shared__ int   s_src[128];

    const int tid  = threadIdx.x;
    const int p0   = blockIdx.x * 128;
    const int oc0  = blockIdx.y * C;
    const int lane = tid & 31, wid = tid >> 5;
    const int g    = lane >> 2, t4 = lane & 3;
    const int px0  = (wid & 3) * 32;
    const int n0   = (wid >> 2) * 48;

    if (tid < 128) {
        int p = p0 + tid; if (p >= HWP) p = HWP - 1;
        int h = p / WW, ww = p % WW;
        int hs = h + SHIFT; if (hs >= HH) hs -= HH;
        int ws = ww + SHIFT; if (ws >= WW) ws -= WW;
        s_src[tid] = hs * WW + ws;
    }
    __syncthreads();

    float pfX[8], pfW[6];
    #pragma unroll
    for (int j = 0; j < 8; j++) {
        int idx = tid + j * 256;
        pfX[j] = x[(idx >> 7) * HWP + s_src[idx & 127]];
    }
    #pragma unroll
    for (int j = 0; j < 6; j++) {
        int idx = tid + j * 256;
        pfW[j] = g_wT[(idx / 96) * C3 + oc0 + idx % 96];
    }

    float acc[2][6][4] = {};

    for (int kc = 0; kc < 6; kc++) {
        __syncthreads();
        #pragma unroll
        for (int j = 0; j < 8; j++) {
            int idx = tid + j * 256;
            int k = idx >> 7, px = idx & 127;
            float hi, lo;
            tf32_split(pfX[j], hi, lo);
            sXhi[k * XS + px] = hi;
            sXlo[k * XS + px] = lo;
        }
        #pragma unroll
        for (int j = 0; j < 6; j++) {
            int idx = tid + j * 256;
            int k = idx / 96, oc = idx % 96;
            float hi, lo;
            tf32_split(pfW[j], hi, lo);
            sWhi[k * WS2 + oc] = hi;
            sWlo[k * WS2 + oc] = lo;
        }
        __syncthreads();
        if (kc < 5) {
            #pragma unroll
            for (int j = 0; j < 8; j++) {
                int idx = tid + j * 256;
                pfX[j] = x[((kc + 1) * 16 + (idx >> 7)) * HWP + s_src[idx & 127]];
            }
            #pragma unroll
            for (int j = 0; j < 6; j++) {
                int idx = tid + j * 256;
                pfW[j] = g_wT[((kc + 1) * 16 + idx / 96) * C3 + oc0 + idx % 96];
            }
        }
        #pragma unroll
        for (int ks = 0; ks < 2; ks++) {
            const int kA = (ks * 8 + t4) * XS;
            const int kB = (ks * 8 + t4 + 4) * XS;
            const int kAw = (ks * 8 + t4) * WS2;
            const int kBw = (ks * 8 + t4 + 4) * WS2;
            uint32_t ah[2][4], al[2][4];
            #pragma unroll
            for (int tm = 0; tm < 2; tm++) {
                int pxb = px0 + 16 * tm + g;
                ah[tm][0] = fb(sXhi[kA + pxb]);
                ah[tm][1] = fb(sXhi[kA + pxb + 8]);
                ah[tm][2] = fb(sXhi[kB + pxb]);
                ah[tm][3] = fb(sXhi[kB + pxb + 8]);
                al[tm][0] = fb(sXlo[kA + pxb]);
                al[tm][1] = fb(sXlo[kA + pxb + 8]);
                al[tm][2] = fb(sXlo[kB + pxb]);
                al[tm][3] = fb(sXlo[kB + pxb + 8]);
            }
            #pragma unroll
            for (int tn = 0; tn < 6; tn++) {
                int nb = n0 + 8 * tn + g;
                uint32_t bh0 = fb(sWhi[kAw + nb]);
                uint32_t bh1 = fb(sWhi[kBw + nb]);
                uint32_t bl0 = fb(sWlo[kAw + nb]);
                uint32_t bl1 = fb(sWlo[kBw + nb]);
                #pragma unroll
                for (int tm = 0; tm < 2; tm++) {
                    MMA_TF32(acc[tm][tn], ah[tm], bh0, bh1);
                    MMA_TF32(acc[tm][tn], al[tm], bh0, bh1);
                    MMA_TF32(acc[tm][tn], ah[tm], bl0, bl1);
                }
            }
        }
    }

    #pragma unroll
    for (int tm = 0; tm < 2; tm++) {
        int pA = p0 + px0 + 16 * tm + g;
        int pB = pA + 8;
        #pragma unroll
        for (int tn = 0; tn < 6; tn++) {
            int n = oc0 + n0 + 8 * tn + 2 * t4;
            float* c = acc[tm][tn];
            if (pA < HWP) {
                g_qkv[n * HWP + pA]       = c[0];
                g_qkv[(n + 1) * HWP + pA] = c[1];
            }
            if (pB < HWP) {
                g_qkv[n * HWP + pB]       = c[2];
                g_qkv[(n + 1) * HWP + pB] = c[3];
            }
        }
    }
}

// --------------------------------------------------------------------------
// K2: depthwise 3x3, pad 1, 288 channels, 8 px per thread (264 = 33*8).
// --------------------------------------------------------------------------
__global__ __launch_bounds__(256) void dwconv_kernel(const float* __restrict__ dww)
{
    const int c = blockIdx.y;
    const int g = blockIdx.x * 256 + threadIdx.x;
    if (g >= HWP / 8) return;
    const int h  = g / 33;
    const int w0 = (g % 33) * 8;
    const float* in = g_qkv + c * HWP;

    float wt[9];
    #pragma unroll
    for (int i = 0; i < 9; i++) wt[i] = __ldg(&dww[c * 9 + i]);

    float o[8] = {};
    #pragma unroll
    for (int ky = 0; ky < 3; ky++) {
        int y = h + ky - 1;
        if ((unsigned)y >= HH) continue;
        const float* b = in + y * WW + w0;
        float4 A = *(const float4*)b;
        float4 B = *(const float4*)(b + 4);
        float L = (w0 > 0) ? __ldg(b - 1) : 0.f;
        float R = (w0 + 8 < WW) ? __ldg(b + 8) : 0.f;
        float v[10] = {L, A.x, A.y, A.z, A.w, B.x, B.y, B.z, B.w, R};
        #pragma unroll
        for (int kx = 0; kx < 3; kx++) {
            float wv = wt[ky * 3 + kx];
            #pragma unroll
            for (int pp = 0; pp < 8; pp++) o[pp] += wv * v[kx + pp];
        }
    }
    float* dst = g_dw + c * HWP + h * WW + w0;
    *(float4*)dst       = make_float4(o[0], o[1], o[2], o[3]);
    *(float4*)(dst + 4) = make_float4(o[4], o[5], o[6], o[7]);
}

// --------------------------------------------------------------------------
// K3: per-(window,head) channel attention via mma.sync tf32 (3xTF32).
// grid (1600,3), 128 threads (4 warps).
//   gram:  C = Q·K^T   M=32 q-ch, N=32 k-ch (8 per warp), K=64 px.
//          A from native [ch][px] stride 68 (=4 mod 32, conflict-free);
//          B from native [ch][px] ([N][K] layout), same stride.
//   AV:    O^T = V^T·G^T  M=64 px, N=32 ch (8 per warp), K=32 d.
//          A = V^T from native [d][px] stride 72 (=8 mod 32);
//          B = G^T from G stored [q-ch][d] stride 36 (=4 mod 32).
// smem ~35KB -> 6 CTAs/SM.
// --------------------------------------------------------------------------
__global__ __launch_bounds__(128) void attn_kernel(const float* __restrict__ temp)
{
    __shared__ float s_buf[8704];    // q/k hi/lo; later V hi/lo + G hi/lo
    __shared__ float s_qn[32], s_kn[32];

    float* qh = s_buf;
    float* ql = s_buf + 2176;        // 32*68
    float* kh = s_buf + 4352;
    float* kl = s_buf + 6528;

    const int tid  = threadIdx.x;
    const int lane = tid & 31, wid = tid >> 5;
    const int g    = lane >> 2, t4 = lane & 3;

    const int win  = blockIdx.x;
    const int head = blockIdx.y;
    const int t    = win >> 6;
    const int w64  = win & 63;
    const int wy = w64 >> 3, wx = w64 & 7;
    const int r0  = c_off[t / 5] + wy * 8;
    const int cc0 = c_off[t % 5] + wx * 8;

    // ---- load q,k (64 ch x 64 px) native [ch][px], tf32-split ----
    for (int i = tid; i < 2048; i += 128) {
        int ch = i >> 5, pr = i & 31;
        int r = pr >> 2, j = (pr & 3) * 2;
        int gch = (ch < 32) ? head * 32 + ch : 96 + head * 32 + (ch - 32);
        float2 v = *(const float2*)&g_dw[gch * HWP + (r0 + r) * WW + cc0 + j];
        int px = r * 8 + j;
        float h0, l0, h1, l1;
        tf32_split(v.x, h0, l0);
        tf32_split(v.y, h1, l1);
        int row = ch & 31;
        float* dh = (ch < 32) ? qh : kh;
        float* dl = (ch < 32) ? ql : kl;
        *(float2*)&dh[row * 68 + px] = make_float2(h0, h1);
        *(float2*)&dl[row * 68 + px] = make_float2(l0, l1);
    }
    __syncthreads();

    // ---- inverse L2 norms (on hi+lo = original fp32 values) ----
    if (tid < 64) {
        const float* rh = (tid < 32) ? (qh + tid * 68) : (kh + (tid - 32) * 68);
        const float* rl = (tid < 32) ? (ql + tid * 68) : (kl + (tid - 32) * 68);
        float s = 0.f;
        #pragma unroll
        for (int p = 0; p < 64; p += 4) {
            float4 a = *(const float4*)&rh[p];
            float4 b = *(const float4*)&rl[p];
            float v0 = a.x + b.x, v1 = a.y + b.y, v2 = a.z + b.z, v3 = a.w + b.w;
            s += v0 * v0 + v1 * v1 + v2 * v2 + v3 * v3;
        }
        float inv = 1.0f / fmaxf(sqrtf(s), 1e-12f);
        if (tid < 32) s_qn[tid] = inv; else s_kn[tid - 32] = inv;
    }
    __syncthreads();

    // ---- gram: warp wid handles k-ch cols [8*wid, 8*wid+8) ----
    float gacc[2][4] = {};
    {
        const int nb = 8 * wid + g;
        #pragma unroll
        for (int kt = 0; kt < 8; kt++) {
            int k0 = kt * 8 + t4;
            uint32_t bh0 = fb(kh[nb * 68 + k0]);
            uint32_t bh1 = fb(kh[nb * 68 + k0 + 4]);
            uint32_t bl0 = fb(kl[nb * 68 + k0]);
            uint32_t bl1 = fb(kl[nb * 68 + k0 + 4]);
            #pragma unroll
            for (int tm = 0; tm < 2; tm++) {
                int m = 16 * tm + g;
                uint32_t ah[4], al[4];
                ah[0] = fb(qh[m * 68 + k0]);
                ah[1] = fb(qh[(m + 8) * 68 + k0]);
                ah[2] = fb(qh[m * 68 + k0 + 4]);
                ah[3] = fb(qh[(m + 8) * 68 + k0 + 4]);
                al[0] = fb(ql[m * 68 + k0]);
                al[1] = fb(ql[(m + 8) * 68 + k0]);
                al[2] = fb(ql[m * 68 + k0 + 4]);
                al[3] = fb(ql[(m + 8) * 68 + k0 + 4]);
                MMA_TF32(gacc[tm], ah, bh0, bh1);
                MMA_TF32(gacc[tm], al, bh0, bh1);
                MMA_TF32(gacc[tm], ah, bl0, bl1);
            }
        }
    }
    // scale + relu (accumulator (row,col) known per thread)
    const float tmp = __ldg(&temp[head]);
    float gvv[2][4];
    {
        const int kc = 8 * wid + 2 * t4;
        float kn0 = s_kn[kc] * tmp, kn1 = s_kn[kc + 1] * tmp;
        #pragma unroll
        for (int tm = 0; tm < 2; tm++) {
            int rA = 16 * tm + g, rB = rA + 8;
            float qa = s_qn[rA], qb = s_qn[rB];
            gvv[tm][0] = fmaxf(gacc[tm][0] * qa * kn0, 0.f);
            gvv[tm][1] = fmaxf(gacc[tm][1] * qa * kn1, 0.f);
            gvv[tm][2] = fmaxf(gacc[tm][2] * qb * kn0, 0.f);
            gvv[tm][3] = fmaxf(gacc[tm][3] * qb * kn1, 0.f);
        }
    }
    __syncthreads();     // all q/k reads done -> overlay V and G

    float* vh = s_buf;               // 32*72
    float* vl = s_buf + 2304;
    float* gh = s_buf + 4608;        // 32*36
    float* gl = s_buf + 5760;

    // store G [q-ch][d] stride 36, split hi/lo
    {
        const int kc = 8 * wid + 2 * t4;
        #pragma unroll
        for (int tm = 0; tm < 2; tm++) {
            int rA = 16 * tm + g, rB = rA + 8;
            float h0, l0, h1, l1;
            tf32_split(gvv[tm][0], h0, l0);
            tf32_split(gvv[tm][1], h1, l1);
            *(float2*)&gh[rA * 36 + kc] = make_float2(h0, h1);
            *(float2*)&gl[rA * 36 + kc] = make_float2(l0, l1);
            tf32_split(gvv[tm][2], h0, l0);
            tf32_split(gvv[tm][3], h1, l1);
            *(float2*)&gh[rB * 36 + kc] = make_float2(h0, h1);
            *(float2*)&gl[rB * 36 + kc] = make_float2(l0, l1);
        }
    }
    // stage V native [d][px] stride 72, split hi/lo
    {
        const float* vsrc = g_dw + (size_t)(192 + head * 32) * HWP;
        for (int i = tid; i < 1024; i += 128) {
            int ch = i >> 5, pr = i & 31;
            int r = pr >> 2, j = (pr & 3) * 2;
            float2 v = *(const float2*)&vsrc[(size_t)ch * HWP + (r0 + r) * WW + cc0 + j];
            int px = r * 8 + j;
            float h0, l0, h1, l1;
            tf32_split(v.x, h0, l0);
            tf32_split(v.y, h1, l1);
            *(float2*)&vh[ch * 72 + px] = make_float2(h0, h1);
            *(float2*)&vl[ch * 72 + px] = make_float2(l0, l1);
        }
    }
    __syncthreads();

    // ---- AV: O^T = V^T G^T; warp wid -> out-ch cols [8*wid, 8*wid+8) ----
    float oacc[4][4] = {};
    {
        const int nb = 8 * wid + g;
        #pragma unroll
        for (int kt = 0; kt < 4; kt++) {
            int k0 = kt * 8 + t4;
            uint32_t bh0 = fb(gh[nb * 36 + k0]);
            uint32_t bh1 = fb(gh[nb * 36 + k0 + 4]);
            uint32_t bl0 = fb(gl[nb * 36 + k0]);
            uint32_t bl1 = fb(gl[nb * 36 + k0 + 4]);
            #pragma unroll
            for (int tm = 0; tm < 4; tm++) {
                int m = 16 * tm + g;
                uint32_t ah[4], al[4];
                ah[0] = fb(vh[k0 * 72 + m]);
                ah[1] = fb(vh[k0 * 72 + m + 8]);
                ah[2] = fb(vh[(k0 + 4) * 72 + m]);
                ah[3] = fb(vh[(k0 + 4) * 72 + m + 8]);
                al[0] = fb(vl[k0 * 72 + m]);
                al[1] = fb(vl[k0 * 72 + m + 8]);
                al[2] = fb(vl[(k0 + 4) * 72 + m]);
                al[3] = fb(vl[(k0 + 4) * 72 + m + 8]);
                MMA_TF32(oacc[tm], ah, bh0, bh1);
                MMA_TF32(oacc[tm], al, bh0, bh1);
                MMA_TF32(oacc[tm], ah, bl0, bl1);
            }
        }
    }
    // epilogue: O^T rows = px (py=px>>3, pxx=px&7), cols = out-ch
    {
        const int ch0 = 8 * wid + 2 * t4;
        float* base = g_out + (size_t)(t * 96 + head * 32) * 4096
                    + (wy * 8) * 64 + wx * 8 + g;
        #pragma unroll
        for (int tm = 0; tm < 4; tm++) {
            // px = 16*tm+g -> py = 2*tm, pxx = g ; px+8 -> py = 2*tm+1
            float* r0p = base + (2 * tm) * 64;
            float* r1p = base + (2 * tm + 1) * 64;
            r0p[(size_t)ch0 * 4096]       = oacc[tm][0];
            r0p[(size_t)(ch0 + 1) * 4096] = oacc[tm][1];
            r1p[(size_t)ch0 * 4096]       = oacc[tm][2];
            r1p[(size_t)(ch0 + 1) * 4096] = oacc[tm][3];
        }
    }
}

// --------------------------------------------------------------------------
// K4: out = proj_w @ (gathered tile avg) via mma.sync tf32 (3xTF32).
// --------------------------------------------------------------------------
__global__ __launch_bounds__(256, 2) void proj_mma_kernel(float* __restrict__ out)
{
    __shared__ float sXhi[16 * XS], sXlo[16 * XS];
    __shared__ float sWhi[16 * WS2], sWlo[16 * WS2];
    __shared__ int   s_toff[128 * 4];
    __shared__ int   s_dst[128];
    __shared__ float s_icnt[128];

    const int tid  = threadIdx.x;
    const int p0   = blockIdx.x * 128;
    const int lane = tid & 31, wid = tid >> 5;
    const int g    = lane >> 2, t4 = lane & 3;
    const int px0  = (wid & 3) * 32;
    const int n0   = (wid >> 2) * 48;

    if (tid < 128) {
        int p = p0 + tid; if (p >= HWP) p = HWP - 1;
        int h = p / WW, ww = p % WW;
        int hd = h + SHIFT; if (hd >= HH) hd -= HH;
        int wd = ww + SHIFT; if (wd >= WW) wd -= WW;
        s_dst[tid] = hd * WW + wd;
        int rt[2], ct[2], nr = 0, nc = 0;
        #pragma unroll
        for (int o = 0; o < 5; o++) {
            int off = c_off[o];
            if (off <= h  && h  < off + 64) rt[nr++] = o;
            if (off <= ww && ww < off + 64) ct[nc++] = o;
        }
        #pragma unroll
        for (int m = 0; m < 4; m++) s_toff[tid * 4 + m] = -1;
        int m = 0;
        for (int a = 0; a < nr; a++)
            for (int b = 0; b < nc; b++) {
                int tt = rt[a] * 5 + ct[b];
                s_toff[tid * 4 + m++] = tt * (96 * 4096)
                    + (h - c_off[rt[a]]) * 64 + (ww - c_off[ct[b]]);
            }
        s_icnt[tid] = 1.0f / (float)(nr * nc);
    }
    __syncthreads();

    float pfX[8], pfW[6];
    #pragma unroll
    for (int j = 0; j < 8; j++) {
        int idx = tid + j * 256;
        int k = idx >> 7, px = idx & 127;
        int cch = k * 4096;
        float s = 0.f;
        #pragma unroll
        for (int m = 0; m < 4; m++) {
            int off = s_toff[px * 4 + m];
            if (off >= 0) s += g_out[off + cch];
        }
        pfX[j] = s;
    }
    #pragma unroll
    for (int j = 0; j < 6; j++) {
        int idx = tid + j * 256;
        pfW[j] = g_pwT[(idx / 96) * C + idx % 96];
    }

    float acc[2][6][4] = {};

    for (int kc = 0; kc < 6; kc++) {
        __syncthreads();
        #pragma unroll
        for (int j = 0; j < 8; j++) {
            int idx = tid + j * 256;
            int k = idx >> 7, px = idx & 127;
            float hi, lo;
            tf32_split(pfX[j] * s_icnt[px], hi, lo);
            sXhi[k * XS + px] = hi;
            sXlo[k * XS + px] = lo;
        }
        #pragma unroll
        for (int j = 0; j < 6; j++) {
            int idx = tid + j * 256;
            int k = idx / 96, oc = idx % 96;
            float hi, lo;
            tf32_split(pfW[j], hi, lo);
            sWhi[k * WS2 + oc] = hi;
            sWlo[k * WS2 + oc] = lo;
        }
        __syncthreads();
        if (kc < 5) {
            #pragma unroll
            for (int j = 0; j < 8; j++) {
                int idx = tid + j * 256;
                int k = idx >> 7, px = idx & 127;
                int cch = ((kc + 1) * 16 + k) * 4096;
                float s = 0.f;
                #pragma unroll
                for (int m = 0; m < 4; m++) {
                    int off = s_toff[px * 4 + m];
                    if (off >= 0) s += g_out[off + cch];
                }
                pfX[j] = s;
            }
            #pragma unroll
            for (int j = 0; j < 6; j++) {
                int idx = tid + j * 256;
                pfW[j] = g_pwT[((kc + 1) * 16 + idx / 96) * C + idx % 96];
            }
        }
        #pragma unroll
        for (int ks = 0; ks < 2; ks++) {
            const int kA = (ks * 8 + t4) * XS;
            const int kB = (ks * 8 + t4 + 4) * XS;
            const int kAw = (ks * 8 + t4) * WS2;
            const int kBw = (ks * 8 + t4 + 4) * WS2;
            uint32_t ah[2][4], al[2][4];
            #pragma unroll
            for (int tm = 0; tm < 2; tm++) {
                int pxb = px0 + 16 * tm + g;
                ah[tm][0] = fb(sXhi[kA + pxb]);
                ah[tm][1] = fb(sXhi[kA + pxb + 8]);
                ah[tm][2] = fb(sXhi[kB + pxb]);
                ah[tm][3] = fb(sXhi[kB + pxb + 8]);
                al[tm][0] = fb(sXlo[kA + pxb]);
                al[tm][1] = fb(sXlo[kA + pxb + 8]);
                al[tm][2] = fb(sXlo[kB + pxb]);
                al[tm][3] = fb(sXlo[kB + pxb + 8]);
            }
            #pragma unroll
            for (int tn = 0; tn < 6; tn++) {
                int nb = n0 + 8 * tn + g;
                uint32_t bh0 = fb(sWhi[kAw + nb]);
                uint32_t bh1 = fb(sWhi[kBw + nb]);
                uint32_t bl0 = fb(sWlo[kAw + nb]);
                uint32_t bl1 = fb(sWlo[kBw + nb]);
                #pragma unroll
                for (int tm = 0; tm < 2; tm++) {
                    MMA_TF32(acc[tm][tn], ah[tm], bh0, bh1);
                    MMA_TF32(acc[tm][tn], al[tm], bh0, bh1);
                    MMA_TF32(acc[tm][tn], ah[tm], bl0, bl1);
                }
            }
        }
    }

    #pragma unroll
    for (int tm = 0; tm < 2; tm++) {
        int lA = px0 + 16 * tm + g;
        int lB = lA + 8;
        #pragma unroll
        for (int tn = 0; tn < 6; tn++) {
            int n = n0 + 8 * tn + 2 * t4;
            float* c = acc[tm][tn];
            if (p0 + lA < HWP) {
                out[n * HWP + s_dst[lA]]       = c[0];
                out[(n + 1) * HWP + s_dst[lA]] = c[1];
            }
            if (p0 + lB < HWP) {
                out[n * HWP + s_dst[lB]]       = c[2];
                out[(n + 1) * HWP + s_dst[lB]] = c[3];
            }
        }
    }
}

// --------------------------------------------------------------------------
extern "C" void kernel_launch(void* const* d_in, const int* in_sizes, int n_in,
                              void* d_out, int out_size)
{
    const float* x    = (const float*)d_in[0];   // (1,96,264,264)
    const float* temp = (const float*)d_in[1];   // (3,1,1)
    const float* qkvw = (const float*)d_in[2];   // (288,96)
    const float* dww  = (const float*)d_in[3];   // (288,1,3,3)
    const float* pw   = (const float*)d_in[4];   // (96,96)
    float* out = (float*)d_out;                  // (1,96,264,264)

    transpose_w_kernel<<<(C3 * C + 255) / 256, 256>>>(qkvw, pw);
    qkv_mma_kernel<<<dim3((HWP + 127) / 128, 3), 256>>>(x);
    dwconv_kernel<<<dim3((HWP / 8 + 255) / 256, C3), 256>>>(dww);
    attn_kernel<<<dim3(1600, 3), 128>>>(temp);
    proj_mma_kernel<<<(HWP + 127) / 128, 256>>>(out);
}